// round 1
// baseline (speedup 1.0000x reference)
#include <cuda_runtime.h>
#include <cuda_bf16.h>

// GPTQLinear: out[16,11008] = x[16,4096] @ W^T + bias, W = (q - z) * s, int4 groups of 128.
// Inputs (metadata order): x f32[16,4096], qweight i32[11008,2048] (one byte/elem, 2 nibbles),
// scales f32[11008,32], zeros f32[11008,32], bias f32[11008]. Output f32[16,11008].

#define OUTF  11008
#define INF   4096
#define NB    16          // batch
#define QI    2048        // packed bytes per output row
#define NG    32          // groups per row
#define ROWS_PER_WARP 4
#define WARPS 8
#define ROWS_PER_BLOCK (ROWS_PER_WARP * WARPS)   // 32
#define NBLOCKS (OUTF / ROWS_PER_BLOCK)          // 344
#define CHUNK_COLS 1024                          // K-chunk in columns
#define CHUNK_BYTES (CHUNK_COLS / 2)             // 512 packed bytes
#define CHUNK_F4 (CHUNK_BYTES * 8)               // 4096 float4 = 64KB

typedef unsigned long long ull;

// Scratch (no allocs allowed): packed/transposed x and fused dequant constants.
// g_xpack[j] is a 128B block for packed-byte index j (columns 2j, 2j+1):
//   float4 q=0..3 : column 2j,   batches 4q..4q+3
//   float4 q=4..7 : column 2j+1, batches 4(q-4)..4(q-4)+3
__device__ float4 g_xpack[QI * 8];
__device__ float2 g_sB[OUTF * NG];   // {s, -z*s}

#define FMA2(acc, a, b) asm("fma.rn.f32x2 %0, %1, %2, %0;" : "+l"(acc) : "l"(a), "l"(b))
#define ADD2(d, a, b)   asm("add.rn.f32x2 %0, %1, %2;" : "=l"(d) : "l"(a), "l"(b))
#define PACKW(d, w) do { unsigned _wu = __float_as_uint(w); \
    asm("mov.b64 %0, {%1, %1};" : "=l"(d) : "r"(_wu)); } while (0)

__global__ void pack_x_kernel(const float* __restrict__ x) {
    int t = blockIdx.x * blockDim.x + threadIdx.x;       // 16384 threads
    if (t >= QI * 8) return;
    int j = t >> 3;
    int q = t & 7;
    int col = 2 * j + (q >> 2);
    int b0 = (q & 3) * 4;
    g_xpack[t] = make_float4(x[(b0 + 0) * INF + col],
                             x[(b0 + 1) * INF + col],
                             x[(b0 + 2) * INF + col],
                             x[(b0 + 3) * INF + col]);
}

__global__ void prep_sb_kernel(const float* __restrict__ scales,
                               const float* __restrict__ zeros) {
    int i = blockIdx.x * blockDim.x + threadIdx.x;       // 352256 threads exactly
    float s = scales[i];
    float z = zeros[i];
    g_sB[i] = make_float2(s, -z * s);
}

extern __shared__ float4 s_x[];   // CHUNK_F4 float4 = 64KB, XOR-swizzled

__global__ __launch_bounds__(256, 2)
void gptq_main_kernel(const int* __restrict__ qw,
                      const float* __restrict__ bias,
                      float* __restrict__ out) {
    const int tid  = threadIdx.x;
    const int lane = tid & 31;
    const int warp = tid >> 5;
    const int o0   = blockIdx.x * ROWS_PER_BLOCK + warp * ROWS_PER_WARP;
    const int xr   = lane & 7;                 // swizzle xor for this lane
    const int* qp  = qw + o0 * QI + lane;      // row base + lane offset

    ull acc[ROWS_PER_WARP][8];
#pragma unroll
    for (int r = 0; r < ROWS_PER_WARP; ++r)
#pragma unroll
        for (int k = 0; k < 8; ++k) acc[r][k] = 0ull;

    for (int c = 0; c < INF / CHUNK_COLS; ++c) {
        // ---- stage x chunk into swizzled smem (coalesced gmem read) ----
        const float4* gsrc = g_xpack + c * CHUNK_F4;
#pragma unroll
        for (int idx = tid; idx < CHUNK_F4; idx += 256)
            s_x[idx ^ ((idx >> 3) & 7)] = gsrc[idx];
        __syncthreads();

#pragma unroll 2
        for (int t = 0; t < CHUNK_BYTES / 32; ++t) {     // 16 byte-iters
            const int jl = t * 32 + lane;                // local packed-byte index
            const float4* xbase = s_x + jl * 8;

            // 128B of x for this byte's two columns: 8 conflict-free LDS.128
            ull xlo0[4], xhi0[4], xlo1[4], xhi1[4];
#pragma unroll
            for (int q = 0; q < 4; ++q) {
                ulonglong2 v = *reinterpret_cast<const ulonglong2*>(xbase + (q ^ xr));
                xlo0[q] = v.x; xhi0[q] = v.y;
            }
#pragma unroll
            for (int q = 0; q < 4; ++q) {
                ulonglong2 v = *reinterpret_cast<const ulonglong2*>(xbase + ((q + 4) ^ xr));
                xlo1[q] = v.x; xhi1[q] = v.y;
            }

            const int g = (c << 3) + (t >> 1);           // uniform group id this iter

#pragma unroll
            for (int r = 0; r < ROWS_PER_WARP; ++r) {
                const int bv = qp[r * QI + c * CHUNK_BYTES + t * 32];
                const float2 sB = g_sB[(o0 + r) * NG + g];
                // exact nibble->float, then w = q*s - z*s (one rounding)
                float q0 = __int_as_float(0x4B000000 | (bv & 15)) - 8388608.0f;
                float q1 = __int_as_float(0x4B000000 | ((bv >> 4) & 15)) - 8388608.0f;
                float w0 = fmaf(q0, sB.x, sB.y);
                float w1 = fmaf(q1, sB.x, sB.y);
                ull w0p, w1p;
                PACKW(w0p, w0);
                PACKW(w1p, w1);
#pragma unroll
                for (int q = 0; q < 4; ++q) {
                    FMA2(acc[r][2 * q],     xlo0[q], w0p);
                    FMA2(acc[r][2 * q + 1], xhi0[q], w0p);
                    FMA2(acc[r][2 * q],     xlo1[q], w1p);
                    FMA2(acc[r][2 * q + 1], xhi1[q], w1p);
                }
            }
        }
        __syncthreads();
    }

    // ---- cross-lane reduction: 64-bit shfl butterfly + packed add ----
#pragma unroll
    for (int r = 0; r < ROWS_PER_WARP; ++r)
#pragma unroll
        for (int k = 0; k < 8; ++k) {
            ull v = acc[r][k];
#pragma unroll
            for (int off = 16; off; off >>= 1) {
                ull u = __shfl_xor_sync(0xffffffffu, v, off);
                ADD2(v, v, u);
            }
            acc[r][k] = v;
        }

    // ---- stage block output tile in smem, then coalesced store ----
    float* so = reinterpret_cast<float*>(s_x);           // [16][32]
#pragma unroll
    for (int r = 0; r < ROWS_PER_WARP; ++r)
#pragma unroll
        for (int k = 0; k < 8; ++k)
            if (lane == r * 8 + k) {
                int col = warp * ROWS_PER_WARP + r;
                so[(2 * k) * ROWS_PER_BLOCK + col] =
                    __uint_as_float((unsigned)(acc[r][k] & 0xffffffffull));
                so[(2 * k + 1) * ROWS_PER_BLOCK + col] =
                    __uint_as_float((unsigned)(acc[r][k] >> 32));
            }
    __syncthreads();

    const int ob = blockIdx.x * ROWS_PER_BLOCK;
#pragma unroll
    for (int idx = tid; idx < NB * ROWS_PER_BLOCK; idx += 256) {
        int b   = idx >> 5;
        int col = idx & 31;
        out[b * OUTF + ob + col] = so[idx] + bias[ob + col];
    }
}

extern "C" void kernel_launch(void* const* d_in, const int* in_sizes, int n_in,
                              void* d_out, int out_size) {
    const float* x      = (const float*)d_in[0];
    const int*   qw     = (const int*)d_in[1];
    const float* scales = (const float*)d_in[2];
    const float* zeros  = (const float*)d_in[3];
    const float* bias   = (const float*)d_in[4];
    float*       out    = (float*)d_out;

    static bool attr_set = false;   // idempotent attribute set (not a work guard)
    if (!attr_set) {
        cudaFuncSetAttribute(gptq_main_kernel,
                             cudaFuncAttributeMaxDynamicSharedMemorySize,
                             CHUNK_F4 * sizeof(float4));
        attr_set = true;
    }

    pack_x_kernel<<<(QI * 8 + 255) / 256, 256>>>(x);
    prep_sb_kernel<<<(OUTF * NG) / 256, 256>>>(scales, zeros);
    gptq_main_kernel<<<NBLOCKS, 256, CHUNK_F4 * sizeof(float4)>>>(qw, bias, out);
}

// round 2
// speedup vs baseline: 1.0205x; 1.0205x over previous
#include <cuda_runtime.h>
#include <cuda_bf16.h>

// GPTQLinear: out[16,11008] = x[16,4096] @ W^T + bias, W = (q - z) * s, int4 groups of 128.
// Inputs: x f32[16,4096], qweight i32[11008,2048] (one byte/elem, 2 nibbles),
// scales f32[11008,32], zeros f32[11008,32], bias f32[11008]. Output f32[16,11008].

#define OUTF  11008
#define INF   4096
#define NB    16
#define QI    2048          // packed bytes per output row
#define NG    32            // groups per row
#define ROWS_PER_WARP 4
#define WARPS 4
#define THREADS (WARPS * 32)                     // 128
#define ROWS_PER_BLOCK (ROWS_PER_WARP * WARPS)   // 16
#define NBLOCKS (OUTF / ROWS_PER_BLOCK)          // 688
#define CHUNK_COLS 512
#define CHUNK_BYTES (CHUNK_COLS / 2)             // 256
#define CHUNK_F4 (CHUNK_BYTES * 8)               // 2048 float4 = 32KB
#define NCHUNKS (INF / CHUNK_COLS)               // 8
#define TITERS (CHUNK_BYTES / 32)                // 8
#define GPC (CHUNK_COLS / 128)                   // groups per chunk = 4

typedef unsigned long long ull;

// Scratch: x transposed to [col][batch] (viewed as float4 blocks), fused dequant consts.
__device__ float4 g_xpack[QI * 8];               // = xT[4096][16] floats
__device__ float2 g_sB[OUTF * NG];               // {s, -z*s}

#define FMA2(acc, a, b) asm("fma.rn.f32x2 %0, %1, %2, %0;" : "+l"(acc) : "l"(a), "l"(b))
#define ADD2(d, a, b)   asm("add.rn.f32x2 %0, %1, %2;" : "=l"(d) : "l"(a), "l"(b))
#define PACKW(d, w) do { unsigned _wu = __float_as_uint(w); \
    asm("mov.b64 %0, {%1, %1};" : "=l"(d) : "r"(_wu)); } while (0)

// Fused prep: blocks [0,64) transpose x into g_xpack; blocks [64,1440) build g_sB.
__global__ void prep_kernel(const float* __restrict__ x,
                            const float* __restrict__ scales,
                            const float* __restrict__ zeros) {
    if (blockIdx.x < 64) {
        __shared__ float tile[NB][65];
        const int c0 = blockIdx.x * 64;
        const int tid = threadIdx.x;
#pragma unroll
        for (int idx = tid; idx < NB * 64; idx += 256) {
            int r = idx >> 6, col = idx & 63;
            tile[r][col] = x[r * INF + c0 + col];
        }
        __syncthreads();
        float* xo = reinterpret_cast<float*>(g_xpack);
#pragma unroll
        for (int idx = tid; idx < NB * 64; idx += 256) {
            int col = idx >> 4, b = idx & 15;
            xo[(c0 + col) * NB + b] = tile[b][col];
        }
    } else {
        int i = (blockIdx.x - 64) * 256 + threadIdx.x;   // exactly OUTF*NG items
        float s = scales[i];
        float z = zeros[i];
        g_sB[i] = make_float2(s, -z * s);
    }
}

extern __shared__ char smem_raw[];

__global__ __launch_bounds__(THREADS, 4)
void gptq_main_kernel(const int* __restrict__ qw,
                      const float* __restrict__ bias,
                      float* __restrict__ out) {
    float4* s_x  = reinterpret_cast<float4*>(smem_raw);             // 32KB, swizzled
    float2* s_sb = reinterpret_cast<float2*>(smem_raw + CHUNK_F4 * 16);  // 16 rows x 4 groups

    const int tid  = threadIdx.x;
    const int lane = tid & 31;
    const int warp = tid >> 5;
    const int rb0  = blockIdx.x * ROWS_PER_BLOCK;       // block row base
    const int o0   = rb0 + warp * ROWS_PER_WARP;        // warp row base
    const int xr   = lane & 7;
    const int* qp  = qw + o0 * QI + lane;

    ull acc[ROWS_PER_WARP][8];
#pragma unroll
    for (int r = 0; r < ROWS_PER_WARP; ++r)
#pragma unroll
        for (int k = 0; k < 8; ++k) acc[r][k] = 0ull;

    for (int c = 0; c < NCHUNKS; ++c) {
        // stage x chunk (XOR-swizzled) + this chunk's dequant consts
        const float4* gsrc = g_xpack + c * CHUNK_F4;
#pragma unroll
        for (int idx = tid; idx < CHUNK_F4; idx += THREADS)
            s_x[idx ^ ((idx >> 3) & 7)] = gsrc[idx];
        if (tid < ROWS_PER_BLOCK * GPC) {               // 64 entries
            int r = tid >> 2, g = tid & 3;
            s_sb[tid] = g_sB[(rb0 + r) * NG + c * GPC + g];
        }
        __syncthreads();

#pragma unroll 2
        for (int t = 0; t < TITERS; ++t) {
            const int jl = t * 32 + lane;
            const float4* xbase = s_x + jl * 8;

            // dequant consts + packed bytes for 4 rows
            ull w0p[ROWS_PER_WARP], w1p[ROWS_PER_WARP];
#pragma unroll
            for (int r = 0; r < ROWS_PER_WARP; ++r) {
                const int bv = qp[r * QI + c * CHUNK_BYTES + t * 32];
                const float2 sB = s_sb[(warp * ROWS_PER_WARP + r) * GPC + (t >> 1)];
                float q0 = __int_as_float(0x4B000000 | (bv & 15)) - 8388608.0f;
                float q1 = __int_as_float(0x4B000000 | ((bv >> 4) & 15)) - 8388608.0f;
                float w0 = fmaf(q0, sB.x, sB.y);
                float w1 = fmaf(q1, sB.x, sB.y);
                PACKW(w0p[r], w0);
                PACKW(w1p[r], w1);
            }

            // even column (low nibble): quads 0..3
#pragma unroll
            for (int q = 0; q < 4; ++q) {
                ulonglong2 v = *reinterpret_cast<const ulonglong2*>(xbase + (q ^ xr));
#pragma unroll
                for (int r = 0; r < ROWS_PER_WARP; ++r) {
                    FMA2(acc[r][2 * q],     v.x, w0p[r]);
                    FMA2(acc[r][2 * q + 1], v.y, w0p[r]);
                }
            }
            // odd column (high nibble): quads 4..7
#pragma unroll
            for (int q = 0; q < 4; ++q) {
                ulonglong2 v = *reinterpret_cast<const ulonglong2*>(xbase + ((q + 4) ^ xr));
#pragma unroll
                for (int r = 0; r < ROWS_PER_WARP; ++r) {
                    FMA2(acc[r][2 * q],     v.x, w1p[r]);
                    FMA2(acc[r][2 * q + 1], v.y, w1p[r]);
                }
            }
        }
        __syncthreads();
    }

    // cross-lane reduction: 64-bit shfl butterfly + packed add
#pragma unroll
    for (int r = 0; r < ROWS_PER_WARP; ++r)
#pragma unroll
        for (int k = 0; k < 8; ++k) {
            ull v = acc[r][k];
#pragma unroll
            for (int off = 16; off; off >>= 1) {
                ull u = __shfl_xor_sync(0xffffffffu, v, off);
                ADD2(v, v, u);
            }
            acc[r][k] = v;
        }

    // stage output tile [16 batches][16 cols] in smem, coalesced store
    float* so = reinterpret_cast<float*>(smem_raw);
#pragma unroll
    for (int r = 0; r < ROWS_PER_WARP; ++r)
#pragma unroll
        for (int k = 0; k < 8; ++k)
            if (lane == r * 8 + k) {
                int col = warp * ROWS_PER_WARP + r;
                so[(2 * k) * ROWS_PER_BLOCK + col] =
                    __uint_as_float((unsigned)(acc[r][k] & 0xffffffffull));
                so[(2 * k + 1) * ROWS_PER_BLOCK + col] =
                    __uint_as_float((unsigned)(acc[r][k] >> 32));
            }
    __syncthreads();

#pragma unroll
    for (int idx = tid; idx < NB * ROWS_PER_BLOCK; idx += THREADS) {
        int b = idx >> 4, col = idx & 15;
        out[b * OUTF + rb0 + col] = so[idx] + bias[rb0 + col];
    }
}

extern "C" void kernel_launch(void* const* d_in, const int* in_sizes, int n_in,
                              void* d_out, int out_size) {
    const float* x      = (const float*)d_in[0];
    const int*   qw     = (const int*)d_in[1];
    const float* scales = (const float*)d_in[2];
    const float* zeros  = (const float*)d_in[3];
    const float* bias   = (const float*)d_in[4];
    float*       out    = (float*)d_out;

    prep_kernel<<<64 + (OUTF * NG) / 256, 256>>>(x, scales, zeros);
    gptq_main_kernel<<<NBLOCKS, THREADS, CHUNK_F4 * 16 + ROWS_PER_BLOCK * GPC * 8>>>(
        qw, bias, out);
}

// round 3
// speedup vs baseline: 1.6891x; 1.6552x over previous
#include <cuda_runtime.h>
#include <cuda_bf16.h>

// GPTQLinear: out[16,11008] = x[16,4096] @ W^T + bias, W = (q - z) * s, int4 groups of 128.
// Inputs: x f32[16,4096], qweight i32[11008,2048] (one byte/elem, 2 nibbles),
// scales f32[11008,32], zeros f32[11008,32], bias f32[11008]. Output f32[16,11008].

#define OUTF  11008
#define INF   4096
#define NB    16
#define QI    2048
#define NG    32
#define ROWS_PER_WARP 4
#define WARPS 4
#define THREADS (WARPS * 32)                     // 128
#define ROWS_PER_BLOCK (ROWS_PER_WARP * WARPS)   // 16
#define NBLOCKS (OUTF / ROWS_PER_BLOCK)          // 688
#define CHUNK_COLS 256
#define CHUNK_BYTES (CHUNK_COLS / 2)             // 128 ints per row per chunk
#define CHUNK_F4 (CHUNK_BYTES * 8)               // 1024 float4 = 16KB x per chunk
#define NCHUNKS (INF / CHUNK_COLS)               // 16
#define TITERS (CHUNK_BYTES / 32)                // 4
#define GPC (CHUNK_COLS / 128)                   // 2 groups per chunk

// smem layout (dynamic): x[2][16KB] | qw[2][8KB] | sb[2][256B]
#define SMEM_SX(buf)  ((buf) * 16384)
#define SMEM_SQW(buf) (32768 + (buf) * 8192)
#define SMEM_SSB(buf) (49152 + (buf) * 256)
#define SMEM_TOTAL    49664

typedef unsigned long long ull;

__device__ float4 g_xpack[QI * 8];               // xT[4096][16] floats
__device__ float2 g_sB[OUTF * NG];               // {s, -z*s}

#define FMA2(acc, a, b) asm("fma.rn.f32x2 %0, %1, %2, %0;" : "+l"(acc) : "l"(a), "l"(b))
#define ADD2(d, a, b)   asm("add.rn.f32x2 %0, %1, %2;" : "=l"(d) : "l"(a), "l"(b))
#define PACKW(d, w) do { unsigned _wu = __float_as_uint(w); \
    asm("mov.b64 %0, {%1, %1};" : "=l"(d) : "r"(_wu)); } while (0)

__device__ __forceinline__ void cp16(unsigned dst, const void* src) {
    asm volatile("cp.async.cg.shared.global [%0], [%1], 16;" :: "r"(dst), "l"(src));
}
__device__ __forceinline__ void cp8(unsigned dst, const void* src) {
    asm volatile("cp.async.ca.shared.global [%0], [%1], 8;" :: "r"(dst), "l"(src));
}

// Fused prep: blocks [0,64) transpose x; blocks [64,1440) build {s,-z*s}.
__global__ void prep_kernel(const float* __restrict__ x,
                            const float* __restrict__ scales,
                            const float* __restrict__ zeros) {
    if (blockIdx.x < 64) {
        __shared__ float tile[NB][65];
        const int c0 = blockIdx.x * 64;
        const int tid = threadIdx.x;
#pragma unroll
        for (int idx = tid; idx < NB * 64; idx += 256) {
            int r = idx >> 6, col = idx & 63;
            tile[r][col] = x[r * INF + c0 + col];
        }
        __syncthreads();
        float* xo = reinterpret_cast<float*>(g_xpack);
#pragma unroll
        for (int idx = tid; idx < NB * 64; idx += 256) {
            int col = idx >> 4, b = idx & 15;
            xo[(c0 + col) * NB + b] = tile[b][col];
        }
    } else {
        int i = (blockIdx.x - 64) * 256 + threadIdx.x;
        float s = scales[i];
        float z = zeros[i];
        g_sB[i] = make_float2(s, -z * s);
    }
}

extern __shared__ char smem_raw[];

__global__ __launch_bounds__(THREADS, 4)
void gptq_main_kernel(const int* __restrict__ qw,
                      const float* __restrict__ bias,
                      float* __restrict__ out) {
    const int tid  = threadIdx.x;
    const int lane = tid & 31;
    const int warp = tid >> 5;
    const int rb0  = blockIdx.x * ROWS_PER_BLOCK;
    const int xr   = lane & 7;

    unsigned smem_u32;
    asm("{ .reg .u64 t; cvta.to.shared.u64 t, %1; cvt.u32.u64 %0, t; }"
        : "=r"(smem_u32) : "l"(smem_raw));

    // ---- async stage of one chunk into buffer buf ----
    auto stage = [&](int c, int buf) {
        unsigned sx = smem_u32 + SMEM_SX(buf);
        const float4* gx = g_xpack + c * CHUNK_F4;
#pragma unroll
        for (int i = 0; i < CHUNK_F4 / THREADS; ++i) {     // 8
            int idx = tid + i * THREADS;
            cp16(sx + (unsigned)((idx ^ ((idx >> 3) & 7)) * 16), gx + idx);
        }
        unsigned sq = smem_u32 + SMEM_SQW(buf);
#pragma unroll
        for (int p = 0; p < 4; ++p) {
            int li = p * 512 + tid * 4;                     // int index in [0,2048)
            int r = li >> 7, i2 = li & 127;
            cp16(sq + (unsigned)(li * 4), qw + (rb0 + r) * QI + c * CHUNK_BYTES + i2);
        }
        if (tid < ROWS_PER_BLOCK * GPC) {                   // 32 float2
            unsigned sb = smem_u32 + SMEM_SSB(buf);
            cp8(sb + (unsigned)(tid * 8),
                &g_sB[(rb0 + (tid >> 1)) * NG + c * GPC + (tid & 1)]);
        }
        asm volatile("cp.async.commit_group;");
    };

    ull acc[ROWS_PER_WARP][8];
#pragma unroll
    for (int r = 0; r < ROWS_PER_WARP; ++r)
#pragma unroll
        for (int k = 0; k < 8; ++k) acc[r][k] = 0ull;

    stage(0, 0);

    for (int c = 0; c < NCHUNKS; ++c) {
        const int buf = c & 1;
        if (c + 1 < NCHUNKS) {
            stage(c + 1, buf ^ 1);
            asm volatile("cp.async.wait_group 1;");
        } else {
            asm volatile("cp.async.wait_group 0;");
        }
        __syncthreads();

        const float4* s_x  = reinterpret_cast<const float4*>(smem_raw + SMEM_SX(buf));
        const int*    s_qw = reinterpret_cast<const int*>(smem_raw + SMEM_SQW(buf))
                             + warp * ROWS_PER_WARP * CHUNK_BYTES;
        const float2* s_sb = reinterpret_cast<const float2*>(smem_raw + SMEM_SSB(buf))
                             + warp * ROWS_PER_WARP * GPC;

#pragma unroll
        for (int t = 0; t < TITERS; ++t) {
            const float4* xbase = s_x + (t * 32 + lane) * 8;

            ull w0p[ROWS_PER_WARP], w1p[ROWS_PER_WARP];
#pragma unroll
            for (int r = 0; r < ROWS_PER_WARP; ++r) {
                const int bv = s_qw[r * CHUNK_BYTES + t * 32 + lane];
                const float2 sB = s_sb[r * GPC + (t >> 1)];
                float q0 = __int_as_float(0x4B000000 | (bv & 15)) - 8388608.0f;
                float q1 = __int_as_float(0x4B000000 | ((bv >> 4) & 15)) - 8388608.0f;
                float w0 = fmaf(q0, sB.x, sB.y);
                float w1 = fmaf(q1, sB.x, sB.y);
                PACKW(w0p[r], w0);
                PACKW(w1p[r], w1);
            }
#pragma unroll
            for (int q = 0; q < 4; ++q) {
                ulonglong2 v = *reinterpret_cast<const ulonglong2*>(xbase + (q ^ xr));
#pragma unroll
                for (int r = 0; r < ROWS_PER_WARP; ++r) {
                    FMA2(acc[r][2 * q],     v.x, w0p[r]);
                    FMA2(acc[r][2 * q + 1], v.y, w0p[r]);
                }
            }
#pragma unroll
            for (int q = 0; q < 4; ++q) {
                ulonglong2 v = *reinterpret_cast<const ulonglong2*>(xbase + ((q + 4) ^ xr));
#pragma unroll
                for (int r = 0; r < ROWS_PER_WARP; ++r) {
                    FMA2(acc[r][2 * q],     v.x, w1p[r]);
                    FMA2(acc[r][2 * q + 1], v.y, w1p[r]);
                }
            }
        }
        __syncthreads();
    }

    // ---- cross-lane reduction: 64-bit shfl butterfly + packed add ----
#pragma unroll
    for (int r = 0; r < ROWS_PER_WARP; ++r)
#pragma unroll
        for (int k = 0; k < 8; ++k) {
            ull v = acc[r][k];
#pragma unroll
            for (int off = 16; off; off >>= 1) {
                ull u = __shfl_xor_sync(0xffffffffu, v, off);
                ADD2(v, v, u);
            }
            acc[r][k] = v;
        }

    // ---- stage output tile [16 batches][16 cols] in smem, coalesced store ----
    float* so = reinterpret_cast<float*>(smem_raw);
#pragma unroll
    for (int r = 0; r < ROWS_PER_WARP; ++r)
#pragma unroll
        for (int k = 0; k < 8; ++k)
            if (lane == r * 8 + k) {
                int col = warp * ROWS_PER_WARP + r;
                so[(2 * k) * ROWS_PER_BLOCK + col] =
                    __uint_as_float((unsigned)(acc[r][k] & 0xffffffffull));
                so[(2 * k + 1) * ROWS_PER_BLOCK + col] =
                    __uint_as_float((unsigned)(acc[r][k] >> 32));
            }
    __syncthreads();

#pragma unroll
    for (int idx = tid; idx < NB * ROWS_PER_BLOCK; idx += THREADS) {
        int b = idx >> 4, col = idx & 15;
        out[b * OUTF + rb0 + col] = so[idx] + bias[rb0 + col];
    }
}

extern "C" void kernel_launch(void* const* d_in, const int* in_sizes, int n_in,
                              void* d_out, int out_size) {
    const float* x      = (const float*)d_in[0];
    const int*   qw     = (const int*)d_in[1];
    const float* scales = (const float*)d_in[2];
    const float* zeros  = (const float*)d_in[3];
    const float* bias   = (const float*)d_in[4];
    float*       out    = (float*)d_out;

    static bool attr_set = false;   // idempotent attribute set (not a work guard)
    if (!attr_set) {
        cudaFuncSetAttribute(gptq_main_kernel,
                             cudaFuncAttributeMaxDynamicSharedMemorySize, SMEM_TOTAL);
        attr_set = true;
    }

    prep_kernel<<<64 + (OUTF * NG) / 256, 256>>>(x, scales, zeros);
    gptq_main_kernel<<<NBLOCKS, THREADS, SMEM_TOTAL>>>(qw, bias, out);
}